// round 1
// baseline (speedup 1.0000x reference)
#include <cuda_runtime.h>
#include <cstdint>

typedef unsigned long long ull;

#define NP 2809          // 53*53 patches
#define LW 53
#define NM 8192          // memories
#define KD 3072          // 3*32*32
#define XPW 84
#define XPC 7056         // 84*84
#define KT 16            // k-tile
#define MARGIN 6.0f

// ---------------- scratch (device globals; no allocations allowed) ----------
__device__ __align__(16) float g_xp[3 * XPC];
__device__ float g_memsq[NM];
__device__ ull   g_best[NP];                    // approx (pass1) key
__device__ ull   g_bestx[NP];                   // exact (rescore) key
__device__ __align__(16) float g_D[(size_t)NP * NM];     // ~92 MB approx distances
__device__ __align__(16) float g_recon[(size_t)NP * KD]; // ~34.5 MB
__device__ unsigned int g_maxord;

// ---------------- helpers ---------------------------------------------------
__device__ __forceinline__ unsigned int ford(float f) {
    unsigned int u = __float_as_uint(f);
    return (u & 0x80000000u) ? ~u : (u | 0x80000000u);
}
__device__ __forceinline__ float fordinv(unsigned int o) {
    unsigned int u = (o & 0x80000000u) ? (o ^ 0x80000000u) : ~o;
    return __uint_as_float(u);
}
__device__ __forceinline__ ull mkkey(float d, int m) {
    return ((ull)ford(d) << 32) | (unsigned int)m;
}
__device__ __forceinline__ void ffma2(ull &d, ull a, ull b) {
    asm("fma.rn.f32x2 %0, %1, %2, %0;" : "+l"(d) : "l"(a), "l"(b));
}
__device__ __forceinline__ ull dup2(float x) {
    ull r; asm("mov.b64 %0, {%1, %1};" : "=l"(r) : "f"(x)); return r;
}
__device__ __forceinline__ float2 unpk(ull v) {
    float2 r; asm("mov.b64 {%0, %1}, %2;" : "=f"(r.x), "=f"(r.y) : "l"(v)); return r;
}

// ---------------- kernel 1: build padded image + init -----------------------
__global__ void k_init(const float* __restrict__ img) {
    int idx = blockIdx.x * blockDim.x + threadIdx.x;
    if (idx < 3 * XPC) {
        int c = idx / XPC, rem = idx - c * XPC;
        int r = rem / XPW, col = rem - r * XPW;
        int h = r - 10, w = col - 10;
        float v = 0.f;
        if ((unsigned)h < 64u && (unsigned)w < 64u) v = img[(h * 64 + w) * 3 + c];
        g_xp[idx] = v;
    }
    if (idx < NP) g_best[idx] = ~0ull;
    if (idx == 0) g_maxord = 0u;
}

// ---------------- kernel 2: mem row squared norms ----------------------------
__global__ void k_memsq(const float* __restrict__ mem) {
    int warp = threadIdx.x >> 5, lane = threadIdx.x & 31;
    int row = blockIdx.x * 8 + warp;
    const float4* p = (const float4*)(mem + (size_t)row * KD);
    float s = 0.f;
#pragma unroll
    for (int t = 0; t < 24; ++t) {           // 24*32*4 = 3072
        float4 v = p[lane + t * 32];
        s += v.x * v.x + v.y * v.y + v.z * v.z + v.w * v.w;
    }
#pragma unroll
    for (int o = 16; o; o >>= 1) s += __shfl_xor_sync(~0u, s, o);
    if (lane == 0) g_memsq[row] = s;
}

// ---------------- kernel 3: pass-1 GEMM (fp32 via FFMA2) + approx argmin ----
// Block tile: 256 patches x 128 mems. 256 threads, micro-tile 16p x 8m,
// p packed in f32x2 pairs. Writes approx D matrix + per-patch min key.
__global__ void __launch_bounds__(256, 1) k_pass1(const float* __restrict__ mem) {
    __shared__ __align__(16) float As[KT][256];
    __shared__ __align__(16) float Bs[KT][128];
    __shared__ int sIJ[256];
    __shared__ ull sRed[256];

    int tid = threadIdx.x;
    int tp = tid & 15, tm = tid >> 4;
    int p0 = blockIdx.x * 256, m0 = blockIdx.y * 128;

    {
        int p = p0 + tid;
        int i = 0, j = 0;
        if (p < NP) { i = p / LW; j = p - i * LW; }
        sIJ[tid] = (i << 16) | j;
        sRed[tid] = ~0ull;
    }
    __syncthreads();

    ull acc[8][8];
#pragma unroll
    for (int u = 0; u < 8; ++u)
#pragma unroll
        for (int j = 0; j < 8; ++j) acc[u][j] = 0ull;

    for (int k0 = 0; k0 < KD; k0 += KT) {
        // fill A tile: As[kk][p_local] = patch value (0 for p >= NP)
#pragma unroll
        for (int t = 0; t < KT; ++t) {
            int k = k0 + t;
            int c = k >> 10, rem = k & 1023, kh = rem >> 5, kw = rem & 31;
            int ij = sIJ[tid];
            float v = 0.f;
            if (p0 + tid < NP)
                v = g_xp[c * XPC + ((ij >> 16) + kh) * XPW + (ij & 0xFFFF) + kw];
            As[t][tid] = v;
        }
        // fill B tile (transposed): Bs[kk][m]
#pragma unroll
        for (int t = 0; t < 2; ++t) {
            int e = tid + t * 256;
            int m = e >> 2, kq = e & 3;
            float4 v = *(const float4*)(mem + (size_t)(m0 + m) * KD + k0 + kq * 4);
            Bs[kq * 4 + 0][m] = v.x; Bs[kq * 4 + 1][m] = v.y;
            Bs[kq * 4 + 2][m] = v.z; Bs[kq * 4 + 3][m] = v.w;
        }
        __syncthreads();
#pragma unroll
        for (int kk = 0; kk < KT; ++kk) {
            ull a2[8];
#pragma unroll
            for (int u = 0; u < 8; ++u)
                a2[u] = *(const ull*)&As[kk][u * 32 + tp * 2];
            float4 b0 = *(const float4*)&Bs[kk][tm * 4];
            float4 b1 = *(const float4*)&Bs[kk][64 + tm * 4];
            ull bd[8] = {dup2(b0.x), dup2(b0.y), dup2(b0.z), dup2(b0.w),
                         dup2(b1.x), dup2(b1.y), dup2(b1.z), dup2(b1.w)};
#pragma unroll
            for (int u = 0; u < 8; ++u)
#pragma unroll
                for (int j = 0; j < 8; ++j) ffma2(acc[u][j], a2[u], bd[j]);
        }
        __syncthreads();
    }

    // epilogue: d = memsq - 2*score, write D, block-reduce per-patch min
    float msq[8];
#pragma unroll
    for (int j = 0; j < 4; ++j) {
        msq[j]     = g_memsq[m0 + tm * 4 + j];
        msq[4 + j] = g_memsq[m0 + 64 + tm * 4 + j];
    }
#pragma unroll
    for (int u = 0; u < 8; ++u) {
        int pla = u * 32 + tp * 2;
        float da[8], db[8];
#pragma unroll
        for (int j = 0; j < 8; ++j) {
            float2 s = unpk(acc[u][j]);
            da[j] = msq[j] - 2.f * s.x;
            db[j] = msq[j] - 2.f * s.y;
        }
        int pa = p0 + pla;
        if (pa < NP) {
            *(float4*)&g_D[(size_t)pa * NM + m0 + tm * 4]      = make_float4(da[0], da[1], da[2], da[3]);
            *(float4*)&g_D[(size_t)pa * NM + m0 + 64 + tm * 4] = make_float4(da[4], da[5], da[6], da[7]);
            ull k = mkkey(da[0], m0 + tm * 4);
#pragma unroll
            for (int j = 1; j < 4; ++j) k = min(k, mkkey(da[j], m0 + tm * 4 + j));
#pragma unroll
            for (int j = 0; j < 4; ++j) k = min(k, mkkey(da[4 + j], m0 + 64 + tm * 4 + j));
            atomicMin(&sRed[pla], k);
        }
        int pb = pa + 1;
        if (pb < NP) {
            *(float4*)&g_D[(size_t)pb * NM + m0 + tm * 4]      = make_float4(db[0], db[1], db[2], db[3]);
            *(float4*)&g_D[(size_t)pb * NM + m0 + 64 + tm * 4] = make_float4(db[4], db[5], db[6], db[7]);
            ull k = mkkey(db[0], m0 + tm * 4);
#pragma unroll
            for (int j = 1; j < 4; ++j) k = min(k, mkkey(db[j], m0 + tm * 4 + j));
#pragma unroll
            for (int j = 0; j < 4; ++j) k = min(k, mkkey(db[4 + j], m0 + 64 + tm * 4 + j));
            atomicMin(&sRed[pla + 1], k);
        }
    }
    __syncthreads();
    if (p0 + tid < NP) atomicMin(&g_best[p0 + tid], sRed[tid]);
}

// ---------------- kernel 4: exact rescore of margin candidates --------------
__global__ void k_rescore(const float* __restrict__ mem) {
    __shared__ __align__(16) float s_patch[KD];
    __shared__ int s_cand[128];
    __shared__ int s_n;
    __shared__ float s_part[8];
    __shared__ ull s_bestk;

    int p = blockIdx.x;
    int tid = threadIdx.x;
    int i = p / LW, j = p - i * LW;
    for (int k = tid; k < KD; k += 256) {
        int c = k >> 10, rem = k & 1023, kh = rem >> 5, kw = rem & 31;
        s_patch[k] = g_xp[c * XPC + (i + kh) * XPW + j + kw];
    }
    if (tid == 0) { s_n = 0; s_bestk = ~0ull; }
    __syncthreads();

    float thr = fordinv((unsigned int)(g_best[p] >> 32)) + MARGIN;
    const float* Drow = &g_D[(size_t)p * NM];
    for (int m = tid; m < NM; m += 256) {
        if (Drow[m] < thr) {
            int pos = atomicAdd(&s_n, 1);
            if (pos < 128) s_cand[pos] = m;
        }
    }
    __syncthreads();
    int n = min(s_n, 128);
    for (int ci = 0; ci < n; ++ci) {
        int m = s_cand[ci];
        const float* mr = mem + (size_t)m * KD;
        float part = 0.f;
        for (int k = tid; k < KD; k += 256) part += s_patch[k] * mr[k];
#pragma unroll
        for (int o = 16; o; o >>= 1) part += __shfl_xor_sync(~0u, part, o);
        if ((tid & 31) == 0) s_part[tid >> 5] = part;
        __syncthreads();
        if (tid == 0) {
            float dot = 0.f;
#pragma unroll
            for (int w = 0; w < 8; ++w) dot += s_part[w];
            float d = g_memsq[m] - 2.f * dot;
            ull k = mkkey(d, m);
            if (k < s_bestk) s_bestk = k;
        }
        __syncthreads();
    }
    if (tid == 0) g_bestx[p] = s_bestk;
}

// ---------------- kernel 5: gather recon rows -------------------------------
__global__ void k_recon(const float* __restrict__ mem2, const int* __restrict__ mapping) {
    int p = blockIdx.x;
    int nn = (int)(g_bestx[p] & 0xFFFFFFFFull);
    int row = mapping[nn];
    const float4* src = (const float4*)(mem2 + (size_t)row * KD);
    float4* dst = (float4*)(g_recon + (size_t)p * KD);
    for (int t = threadIdx.x; t < KD / 4; t += 256) dst[t] = src[t];
}

// ---------------- kernel 6: overlap-add (gather form) + block max -----------
__global__ void k_overlap(float* __restrict__ out) {
    __shared__ __align__(16) float s[LW * 32];
    __shared__ float red[4][64];
    int bc = blockIdx.x;
    int c = bc >> 6, h = bc & 63;
    int r = h + 10;
    int tid = threadIdx.x;
    int w = tid & 63, grp = tid >> 6;
    int cc = w + 10;
    int jmin = max(0, cc - 31), jmax = min(LW - 1, cc);
    int ilo = max(0, r - 31), ihi = min(LW - 1, r);

    float sum = 0.f;
    for (int i = ilo; i <= ihi; ++i) {
        int kh = r - i;
        __syncthreads();
        for (int e = tid; e < LW * 8; e += 256) {
            int jj = e >> 3, q = e & 7;
            *(float4*)&s[jj * 32 + q * 4] =
                *(const float4*)&g_recon[(size_t)(i * LW + jj) * KD + c * 1024 + kh * 32 + q * 4];
        }
        __syncthreads();
        for (int jx = jmin + grp; jx <= jmax; jx += 4)
            sum += s[jx * 32 + (cc - jx)];
    }
    red[grp][w] = sum;
    __syncthreads();
    if (tid < 64) {
        float v = red[0][tid] + red[1][tid] + red[2][tid] + red[3][tid];
        out[(h * 64 + tid) * 3 + c] = v;
        red[0][tid] = v;
    }
    __syncthreads();
    if (tid == 0) {
        float mx = red[0][0];
        for (int t = 1; t < 64; ++t) mx = fmaxf(mx, red[0][t]);
        atomicMax(&g_maxord, ford(mx));
    }
}

// ---------------- kernel 7: normalize by global max -------------------------
__global__ void k_norm(float* __restrict__ out) {
    int idx = blockIdx.x * blockDim.x + threadIdx.x;
    if (idx < 64 * 64 * 3) out[idx] = out[idx] / fordinv(g_maxord);
}

// ---------------- launch -----------------------------------------------------
extern "C" void kernel_launch(void* const* d_in, const int* in_sizes, int n_in,
                              void* d_out, int out_size) {
    const float* img     = (const float*)d_in[0];
    const float* mem     = (const float*)d_in[1];
    const float* mem2    = (const float*)d_in[2];
    const int*   mapping = (const int*)d_in[3];
    float* out = (float*)d_out;

    k_init<<<(3 * XPC + 255) / 256, 256>>>(img);
    k_memsq<<<NM / 8, 256>>>(mem);
    dim3 g3((NP + 255) / 256, NM / 128);
    k_pass1<<<g3, 256>>>(mem);
    k_rescore<<<NP, 256>>>(mem);
    k_recon<<<NP, 256>>>(mem2, mapping);
    k_overlap<<<192, 256>>>(out);
    k_norm<<<48, 256>>>(out);
}

// round 4
// speedup vs baseline: 4.5626x; 4.5626x over previous
#include <cuda_runtime.h>
#include <cuda_bf16.h>
#include <mma.h>
#include <cstdint>

using namespace nvcuda;
typedef unsigned long long ull;

#define NP 2809          // 53*53 patches
#define NPAD 2816        // 22*128
#define LW 53
#define NM 8192          // memories
#define KD 3072          // 3*32*32
#define XPW 84
#define XPC 7056         // 84*84
#define MARGIN 12.0f

#define BM 128
#define BN 128
#define BK 32
#define KSTEPS (KD / BK)   // 96
#define LDT 40             // smem tile leading dim (halves): 32 + 8 pad

// ---------------- scratch (device globals; no allocations allowed) ----------
__device__ __align__(16) float g_xp[3 * XPC];
__device__ float g_memsq[NM];
__device__ ull   g_best[NP];                    // approx (pass1) key
__device__ ull   g_bestx[NP];                   // exact (rescore) key
__device__ __align__(16) float g_D[(size_t)NP * NM];       // ~92 MB approx distances
__device__ __align__(16) float g_recon[(size_t)NP * KD];   // ~34.5 MB
__device__ __align__(16) __nv_bfloat16 g_A[(size_t)NPAD * KD];   // 17.3 MB
__device__ __align__(16) __nv_bfloat16 g_Bb[(size_t)NM * KD];    // 50 MB
__device__ unsigned int g_maxord;

// ---------------- helpers ---------------------------------------------------
__device__ __forceinline__ unsigned int ford(float f) {
    unsigned int u = __float_as_uint(f);
    return (u & 0x80000000u) ? ~u : (u | 0x80000000u);
}
__device__ __forceinline__ float fordinv(unsigned int o) {
    unsigned int u = (o & 0x80000000u) ? (o ^ 0x80000000u) : ~o;
    return __uint_as_float(u);
}
__device__ __forceinline__ ull mkkey(float d, int m) {
    return ((ull)ford(d) << 32) | (unsigned int)m;
}
__device__ __forceinline__ uint32_t s2u(const void* p) {
    uint32_t a;
    asm("{ .reg .u64 t; cvta.to.shared.u64 t, %1; cvt.u32.u64 %0, t; }" : "=r"(a) : "l"(p));
    return a;
}
__device__ __forceinline__ uint32_t packbf2(float a, float b) {
    return ((uint32_t)__bfloat16_as_ushort(__float2bfloat16(b)) << 16) |
           (uint32_t)__bfloat16_as_ushort(__float2bfloat16(a));
}

// ---------------- kernel 1: build padded image + init -----------------------
__global__ void k_init(const float* __restrict__ img) {
    int idx = blockIdx.x * blockDim.x + threadIdx.x;
    if (idx < 3 * XPC) {
        int c = idx / XPC, rem = idx - c * XPC;
        int r = rem / XPW, col = rem - r * XPW;
        int h = r - 10, w = col - 10;
        float v = 0.f;
        if ((unsigned)h < 64u && (unsigned)w < 64u) v = img[(h * 64 + w) * 3 + c];
        g_xp[idx] = v;
    }
    if (idx < NP) g_best[idx] = ~0ull;
    if (idx == 0) g_maxord = 0u;
}

// ---------------- kernel 2: build bf16 A matrix (patches) -------------------
__global__ void k_buildA() {
    int e = blockIdx.x * blockDim.x + threadIdx.x;
    if (e >= NPAD * (KD / 8)) return;
    int m = e / (KD / 8), r = e - m * (KD / 8);
    int k = r * 8;
    uint32_t w0 = 0, w1 = 0, w2 = 0, w3 = 0;
    if (m < NP) {
        int i = m / LW, j = m - i * LW;
        int c = k >> 10, rem = k & 1023, kh = rem >> 5, kw = rem & 31;
        const float* src = &g_xp[c * XPC + (i + kh) * XPW + j + kw];
        w0 = packbf2(src[0], src[1]);
        w1 = packbf2(src[2], src[3]);
        w2 = packbf2(src[4], src[5]);
        w3 = packbf2(src[6], src[7]);
    }
    *(uint4*)&g_A[(size_t)m * KD + k] = make_uint4(w0, w1, w2, w3);
}

// ---------------- kernel 3: convert mem to bf16 -----------------------------
__global__ void k_bconv(const float* __restrict__ mem) {
    int e = blockIdx.x * blockDim.x + threadIdx.x;
    if (e >= NM * (KD / 8)) return;
    size_t base = (size_t)e * 8;
    float4 v0 = *(const float4*)(mem + base);
    float4 v1 = *(const float4*)(mem + base + 4);
    *(uint4*)&g_Bb[base] = make_uint4(packbf2(v0.x, v0.y), packbf2(v0.z, v0.w),
                                      packbf2(v1.x, v1.y), packbf2(v1.z, v1.w));
}

// ---------------- kernel 4: mem row squared norms ----------------------------
__global__ void k_memsq(const float* __restrict__ mem) {
    int warp = threadIdx.x >> 5, lane = threadIdx.x & 31;
    int row = blockIdx.x * 8 + warp;
    const float4* p = (const float4*)(mem + (size_t)row * KD);
    float s = 0.f;
#pragma unroll
    for (int t = 0; t < 24; ++t) {
        float4 v = p[lane + t * 32];
        s += v.x * v.x + v.y * v.y + v.z * v.z + v.w * v.w;
    }
#pragma unroll
    for (int o = 16; o; o >>= 1) s += __shfl_xor_sync(~0u, s, o);
    if (lane == 0) g_memsq[row] = s;
}

// ---------------- kernel 5: bf16 wmma GEMM + approx argmin + D write --------
// CTA 128x128, BK=32, cp.async double-buffered. 8 warps (4M x 2N),
// warp tile 32x64 = 2x4 wmma 16x16x16 fragments, fp32 accumulate.
__global__ void __launch_bounds__(256) k_gemm() {
    __shared__ __align__(16) __nv_bfloat16 sA[2][BM * LDT];  // 20480 B
    __shared__ __align__(16) __nv_bfloat16 sB[2][BN * LDT];  // 20480 B
    __shared__ float s_msq[BN];

    int tid = threadIdx.x;
    int w = tid >> 5, lane = tid & 31;
    int warp_m = w & 3, warp_n = w >> 2;
    int p0 = blockIdx.x * BM, m0 = blockIdx.y * BN;

    if (tid < BN) s_msq[tid] = g_memsq[m0 + tid];

    auto load_stage = [&](int st, int k0) {
#pragma unroll
        for (int i = 0; i < 2; ++i) {
            int ch = tid + i * 256;                 // 512 chunks: 128 rows x 4
            int row = ch >> 2, c = ch & 3;          // c*8 halves = c*16 bytes
            uint32_t dA = s2u(&sA[st][row * LDT + c * 8]);
            const void* srcA = &g_A[(size_t)(p0 + row) * KD + k0 + c * 8];
            asm volatile("cp.async.cg.shared.global [%0], [%1], 16;" :: "r"(dA), "l"(srcA));
            uint32_t dB = s2u(&sB[st][row * LDT + c * 8]);
            const void* srcB = &g_Bb[(size_t)(m0 + row) * KD + k0 + c * 8];
            asm volatile("cp.async.cg.shared.global [%0], [%1], 16;" :: "r"(dB), "l"(srcB));
        }
        asm volatile("cp.async.commit_group;");
    };

    wmma::fragment<wmma::accumulator, 16, 16, 16, float> acc[2][4];
#pragma unroll
    for (int fm = 0; fm < 2; ++fm)
#pragma unroll
        for (int fn = 0; fn < 4; ++fn) wmma::fill_fragment(acc[fm][fn], 0.f);

    load_stage(0, 0);
    for (int kt = 0; kt < KSTEPS; ++kt) {
        int cur = kt & 1;
        if (kt + 1 < KSTEPS) {
            load_stage(cur ^ 1, (kt + 1) * BK);
            asm volatile("cp.async.wait_group 1;");
        } else {
            asm volatile("cp.async.wait_group 0;");
        }
        __syncthreads();
#pragma unroll
        for (int ks = 0; ks < 2; ++ks) {
            wmma::fragment<wmma::matrix_a, 16, 16, 16, __nv_bfloat16, wmma::row_major> af[2];
            wmma::fragment<wmma::matrix_b, 16, 16, 16, __nv_bfloat16, wmma::col_major> bf[4];
#pragma unroll
            for (int fm = 0; fm < 2; ++fm)
                wmma::load_matrix_sync(af[fm],
                    &sA[cur][(warp_m * 32 + fm * 16) * LDT + ks * 16], LDT);
#pragma unroll
            for (int fn = 0; fn < 4; ++fn)
                wmma::load_matrix_sync(bf[fn],
                    &sB[cur][(warp_n * 64 + fn * 16) * LDT + ks * 16], LDT);
#pragma unroll
            for (int fm = 0; fm < 2; ++fm)
#pragma unroll
                for (int fn = 0; fn < 4; ++fn)
                    wmma::mma_sync(acc[fm][fn], af[fm], bf[fn], acc[fm][fn]);
        }
        __syncthreads();
    }

    // epilogue: stage each 16x16 acc through smem; d = memsq - 2*score
    float* ebuf = (float*)&sA[0][0] + w * 16 * 20;    // per-warp [16][20] floats
    int r = lane >> 1, cg = lane & 1;
#pragma unroll
    for (int fm = 0; fm < 2; ++fm) {
        int p = p0 + warp_m * 32 + fm * 16 + r;
        bool valid = p < NP;
        ull key = ~0ull;
#pragma unroll
        for (int fn = 0; fn < 4; ++fn) {
            wmma::store_matrix_sync(ebuf, acc[fm][fn], 20, wmma::mem_row_major);
            __syncwarp();
            int nloc = warp_n * 64 + fn * 16 + cg * 8;
            int mcol = m0 + nloc;
            float dv[8];
#pragma unroll
            for (int j = 0; j < 8; ++j) {
                float s = ebuf[r * 20 + cg * 8 + j];
                dv[j] = s_msq[nloc + j] - 2.f * s;
                key = min(key, mkkey(dv[j], mcol + j));
            }
            if (valid) {
                *(float4*)&g_D[(size_t)p * NM + mcol]     = make_float4(dv[0], dv[1], dv[2], dv[3]);
                *(float4*)&g_D[(size_t)p * NM + mcol + 4] = make_float4(dv[4], dv[5], dv[6], dv[7]);
            }
            __syncwarp();
        }
        if (valid) atomicMin(&g_best[p], key);
    }
}

// ---------------- kernel 6: exact rescore of margin candidates --------------
__global__ void k_rescore(const float* __restrict__ mem) {
    __shared__ __align__(16) float s_patch[KD];
    __shared__ int s_cand[128];
    __shared__ int s_n;
    __shared__ float s_part[8];
    __shared__ ull s_bestk;

    int p = blockIdx.x;
    int tid = threadIdx.x;
    int i = p / LW, j = p - i * LW;
    for (int k = tid; k < KD; k += 256) {
        int c = k >> 10, rem = k & 1023, kh = rem >> 5, kw = rem & 31;
        s_patch[k] = g_xp[c * XPC + (i + kh) * XPW + j + kw];
    }
    if (tid == 0) { s_n = 0; s_bestk = ~0ull; }
    __syncthreads();

    float thr = fordinv((unsigned int)(g_best[p] >> 32)) + MARGIN;
    const float* Drow = &g_D[(size_t)p * NM];
    for (int m = tid; m < NM; m += 256) {
        if (Drow[m] < thr) {
            int pos = atomicAdd(&s_n, 1);
            if (pos < 128) s_cand[pos] = m;
        }
    }
    __syncthreads();
    int n = min(s_n, 128);
    for (int ci = 0; ci < n; ++ci) {
        int m = s_cand[ci];
        const float* mr = mem + (size_t)m * KD;
        float part = 0.f;
        for (int k = tid; k < KD; k += 256) part += s_patch[k] * mr[k];
#pragma unroll
        for (int o = 16; o; o >>= 1) part += __shfl_xor_sync(~0u, part, o);
        if ((tid & 31) == 0) s_part[tid >> 5] = part;
        __syncthreads();
        if (tid == 0) {
            float dot = 0.f;
#pragma unroll
            for (int w = 0; w < 8; ++w) dot += s_part[w];
            float d = g_memsq[m] - 2.f * dot;
            ull k = mkkey(d, m);
            if (k < s_bestk) s_bestk = k;
        }
        __syncthreads();
    }
    if (tid == 0) g_bestx[p] = s_bestk;
}

// ---------------- kernel 7: gather recon rows -------------------------------
__global__ void k_recon(const float* __restrict__ mem2, const int* __restrict__ mapping) {
    int p = blockIdx.x;
    int nn = (int)(g_bestx[p] & 0xFFFFFFFFull);
    int row = mapping[nn];
    const float4* src = (const float4*)(mem2 + (size_t)row * KD);
    float4* dst = (float4*)(g_recon + (size_t)p * KD);
    for (int t = threadIdx.x; t < KD / 4; t += 256) dst[t] = src[t];
}

// ---------------- kernel 8: overlap-add (gather form) + block max -----------
__global__ void k_overlap(float* __restrict__ out) {
    __shared__ __align__(16) float s[LW * 32];
    __shared__ float red[4][64];
    int bc = blockIdx.x;
    int c = bc >> 6, h = bc & 63;
    int r = h + 10;
    int tid = threadIdx.x;
    int w = tid & 63, grp = tid >> 6;
    int cc = w + 10;
    int jmin = max(0, cc - 31), jmax = min(LW - 1, cc);
    int ilo = max(0, r - 31), ihi = min(LW - 1, r);

    float sum = 0.f;
    for (int i = ilo; i <= ihi; ++i) {
        int kh = r - i;
        __syncthreads();
        for (int e = tid; e < LW * 8; e += 256) {
            int jj = e >> 3, q = e & 7;
            *(float4*)&s[jj * 32 + q * 4] =
                *(const float4*)&g_recon[(size_t)(i * LW + jj) * KD + c * 1024 + kh * 32 + q * 4];
        }
        __syncthreads();
        for (int jx = jmin + grp; jx <= jmax; jx += 4)
            sum += s[jx * 32 + (cc - jx)];
    }
    red[grp][w] = sum;
    __syncthreads();
    if (tid < 64) {
        float v = red[0][tid] + red[1][tid] + red[2][tid] + red[3][tid];
        out[(h * 64 + tid) * 3 + c] = v;
        red[0][tid] = v;
    }
    __syncthreads();
    if (tid == 0) {
        float mx = red[0][0];
        for (int t = 1; t < 64; ++t) mx = fmaxf(mx, red[0][t]);
        atomicMax(&g_maxord, ford(mx));
    }
}

// ---------------- kernel 9: normalize by global max -------------------------
__global__ void k_norm(float* __restrict__ out) {
    int idx = blockIdx.x * blockDim.x + threadIdx.x;
    if (idx < 64 * 64 * 3) out[idx] = out[idx] / fordinv(g_maxord);
}

// ---------------- launch -----------------------------------------------------
extern "C" void kernel_launch(void* const* d_in, const int* in_sizes, int n_in,
                              void* d_out, int out_size) {
    const float* img     = (const float*)d_in[0];
    const float* mem     = (const float*)d_in[1];
    const float* mem2    = (const float*)d_in[2];
    const int*   mapping = (const int*)d_in[3];
    float* out = (float*)d_out;

    k_init<<<(3 * XPC + 255) / 256, 256>>>(img);
    k_buildA<<<(NPAD * (KD / 8) + 255) / 256, 256>>>();
    k_bconv<<<(NM * (KD / 8) + 255) / 256, 256>>>(mem);
    k_memsq<<<NM / 8, 256>>>(mem);
    dim3 gg(NPAD / BM, NM / BN);
    k_gemm<<<gg, 256>>>();
    k_rescore<<<NP, 256>>>(mem);
    k_recon<<<NP, 256>>>(mem2, mapping);
    k_overlap<<<192, 256>>>(out);
    k_norm<<<48, 256>>>(out);
}